// round 7
// baseline (speedup 1.0000x reference)
#include <cuda_runtime.h>
#include <cstdint>
#include <math.h>

#define BN 2048
#define DN 3072
#define CN 10
#define MN 9

#define ALPHA  0.999999f             // 1 - C*NUM_STAB
#define NST    1e-7f
#define RS10   0.31622776601683794f  // 1/sqrt(10)

typedef unsigned long long u64;
typedef unsigned int u32;

// packed fp32x2 FMA: acc.{lo,hi} += a.{lo,hi} * b.{lo,hi}
#define FMA_X2(acc, a, b) \
    asm("fma.rn.f32x2 %0, %1, %2, %0;" : "+l"(acc) : "l"(a), "l"(b))
#define UNPACK_X2(lo, hi, v) \
    asm("mov.b64 {%0, %1}, %2;" : "=f"(lo), "=f"(hi) : "l"(v))

#define CP_ASYNC16(dst, src) \
    asm volatile("cp.async.cg.shared.global [%0], [%1], 16;" :: "r"(dst), "l"(src))
#define CP_COMMIT() asm volatile("cp.async.commit_group;")
#define CP_WAIT0()  asm volatile("cp.async.wait_group 0;")

// Scratch (no allocations allowed)
__device__ __align__(16) float g_Wt[CN * DN];    // W transposed [C][D]
__device__ float g_Wg[CN * CN];                  // W^T W

// ---------------------------------------------------------------------------
// Prep: blocks 0..11 transpose W -> Wt; blocks 12..21 compute Wg rows.
// ---------------------------------------------------------------------------
__global__ void __launch_bounds__(256) prep_kernel(const float* __restrict__ W) {
    int bid = blockIdx.x;
    int tid = threadIdx.x;
    if (bid < 12) {
        int d = bid * 256 + tid;
        float w[CN];
        #pragma unroll
        for (int c = 0; c < CN; c++) w[c] = __ldg(&W[d * CN + c]);
        #pragma unroll
        for (int c = 0; c < CN; c++) g_Wt[c * DN + d] = w[c];
    } else {
        int i = bid - 12;
        float acc[CN];
        #pragma unroll
        for (int j = 0; j < CN; j++) acc[j] = 0.f;
        for (int d = tid; d < DN; d += 256) {
            float w[CN];
            #pragma unroll
            for (int j = 0; j < CN; j++) w[j] = __ldg(&W[d * CN + j]);
            float wi = w[i];
            #pragma unroll
            for (int j = 0; j < CN; j++) acc[j] = fmaf(wi, w[j], acc[j]);
        }
        #pragma unroll
        for (int j = 0; j < CN; j++) {
            #pragma unroll
            for (int off = 16; off > 0; off >>= 1)
                acc[j] += __shfl_xor_sync(0xffffffffu, acc[j], off);
        }
        __shared__ float smem[8][CN];
        int w_ = tid >> 5, l = tid & 31;
        if (l == 0) {
            #pragma unroll
            for (int j = 0; j < CN; j++) smem[w_][j] = acc[j];
        }
        __syncthreads();
        if (tid < CN) {
            float s = 0.f;
            #pragma unroll
            for (int k = 0; k < 8; k++) s += smem[k][tid];
            g_Wg[i * CN + tid] = s;
        }
    }
}

// ---------------------------------------------------------------------------
// Main kernel (fully fused): 256 blocks x 384 threads, 8 samples/block,
// full K per block. The 8 sample rows are CONTIGUOUS in gmem (96KB), staged
// with one linear cp.async sweep (16 float4 per thread).
// wid = kidx 0..11 (64-float4 K slice); lane = pgrp(2b)|klane(3b).
// W via __ldg: smem 96KB -> L1 carveout ~126KB >= 120KB W => L1-resident.
// Epilogue fused: in-block k-reduce + per-sample closed-form math.
// ---------------------------------------------------------------------------
extern __shared__ __align__(16) float4 xsm[];    // [8 samples][768 float4] = 96KB

__global__ void __launch_bounds__(384, 1) main_kernel(const float* __restrict__ data,
                                                      const float* __restrict__ bias,
                                                      float* __restrict__ out) {
    __shared__ float smred[12][8][CN];           // [kidx][sample][class]
    __shared__ float smlog[8][CN];               // logits

    const int tid   = threadIdx.x;
    const int wid   = tid >> 5;                  // kidx 0..11
    const int lane  = tid & 31;
    const int pgrp  = lane >> 3;                 // sample pair 0..3
    const int klane = lane & 7;

    const int s0 = blockIdx.x * 8;

    // ---- stage 96KB contiguous x block: 6144 float4, 16 per thread --------
    const u32 xsa = (u32)__cvta_generic_to_shared(xsm);
    const float4* __restrict__ xg = reinterpret_cast<const float4*>(data) + (size_t)s0 * 768;
    #pragma unroll
    for (int k = 0; k < 16; k++) {
        int idx = k * 384 + tid;
        CP_ASYNC16(xsa + idx * 16, xg + idx);
    }
    CP_COMMIT();
    CP_WAIT0();
    __syncthreads();

    // ---- compute: warp = K slice (64 float4) across 8 samples -------------
    const int ls = pgrp * 2;
    const int kw = wid * 64 + klane;             // float4 index in K
    const ulonglong2* __restrict__ xs = reinterpret_cast<const ulonglong2*>(xsm);
    const ulonglong2* __restrict__ x0 = xs + (size_t)ls * 768 + kw;
    const ulonglong2* __restrict__ wt = reinterpret_cast<const ulonglong2*>(g_Wt);

    u64 a0[CN], a1[CN];
    #pragma unroll
    for (int c = 0; c < CN; c++) { a0[c] = 0ull; a1[c] = 0ull; }

    #pragma unroll
    for (int i = 0; i < 8; i++) {
        ulonglong2 xv0 = x0[i * 8];
        ulonglong2 xv1 = x0[768 + i * 8];
        #pragma unroll
        for (int c = 0; c < CN; c++) {
            ulonglong2 wv = __ldg(&wt[c * 768 + kw + i * 8]);
            FMA_X2(a0[c], xv0.x, wv.x);
            FMA_X2(a0[c], xv0.y, wv.y);
            FMA_X2(a1[c], xv1.x, wv.x);
            FMA_X2(a1[c], xv1.y, wv.y);
        }
    }

    float f0[CN], f1[CN];
    #pragma unroll
    for (int c = 0; c < CN; c++) {
        float lo, hi;
        UNPACK_X2(lo, hi, a0[c]); f0[c] = lo + hi;
        UNPACK_X2(lo, hi, a1[c]); f1[c] = lo + hi;
    }
    #pragma unroll
    for (int c = 0; c < CN; c++) {
        #pragma unroll
        for (int off = 4; off > 0; off >>= 1) {
            f0[c] += __shfl_xor_sync(0xffffffffu, f0[c], off);
            f1[c] += __shfl_xor_sync(0xffffffffu, f1[c], off);
        }
    }
    if (klane == 0) {
        #pragma unroll
        for (int c = 0; c < CN; c++) {
            smred[wid][ls][c]     = f0[c];
            smred[wid][ls + 1][c] = f1[c];
        }
    }
    __syncthreads();

    // ---- cross-warp k-reduce: 80 threads, one (sample, class) each --------
    if (tid < 80) {
        int s = tid / CN, c = tid - s * CN;
        float a = __ldg(&bias[c]);
        #pragma unroll
        for (int k = 0; k < 12; k++) a += smred[k][s][c];
        smlog[s][c] = a;
    }
    __syncthreads();

    // ---- per-sample epilogue: 8 threads ------------------------------------
    if (tid < 8) {
        float l[CN];
        #pragma unroll
        for (int c = 0; c < CN; c++) l[c] = smlog[tid][c];

        float mx = l[0];
        #pragma unroll
        for (int c = 1; c < CN; c++) mx = fmaxf(mx, l[c]);

        float e[CN], Z = 0.f;
        #pragma unroll
        for (int c = 0; c < CN; c++) { e[c] = expf(l[c] - mx); Z += e[c]; }
        float invZ = 1.f / Z;

        float s[CN], r[CN], sumr = 0.f;
        #pragma unroll
        for (int c = 0; c < CN; c++) {
            s[c] = e[c] * invZ;
            float p = fmaf(s[c], ALPHA, NST);
            r[c] = sqrtf(p);
            sumr += r[c];
        }
        float u = 1.f - r[MN];
        float delta = 2.f * acosf(fminf(sumr * RS10, 1.f));

        float wg[CN * CN];
        #pragma unroll
        for (int v = 0; v < CN * CN; v++) wg[v] = __ldg(&g_Wg[v]);

        float q[CN];
        #pragma unroll
        for (int j = 0; j < CN; j++) {
            float a = 0.f;
            #pragma unroll
            for (int k = 0; k < CN; k++) a = fmaf(s[k], wg[k * CN + j], a);
            q[j] = a;
        }
        float qs = 0.f;
        #pragma unroll
        for (int j = 0; j < CN; j++) qs = fmaf(q[j], s[j], qs);

        float inv_u = 1.f / u;
        float c2com = ALPHA * s[MN] * inv_u * inv_u / r[MN];
        float c1[MN], c2[MN], t[MN];
        #pragma unroll
        for (int m = 0; m < MN; m++) {
            c1[m] = ALPHA * s[m] * inv_u / r[m];
            c2[m] = c2com * r[m];
            t[m]  = c1[m] + c2[m];
        }

        float col[MN];
        #pragma unroll
        for (int n = 0; n < MN; n++) col[n] = 0.f;
        float norminf = 0.f;

        #pragma unroll
        for (int m = 0; m < MN; m++) {
            float Mrow[CN];
            #pragma unroll
            for (int j = 0; j < CN; j++)
                Mrow[j] = c1[m] * wg[m * CN + j] + c2[m] * wg[MN * CN + j] - t[m] * q[j];
            float wm = c1[m] * q[m] + c2[m] * q[MN] - t[m] * qs;
            float rowsum = 0.f;
            #pragma unroll
            for (int n = 0; n < MN; n++) {
                float g2 = c1[n] * Mrow[n] + c2[n] * Mrow[MN] - t[n] * wm;
                float ag = fabsf(g2);
                rowsum += ag;
                col[n] += ag;
            }
            norminf = fmaxf(norminf, rowsum);
        }
        float norm1 = 0.f;
        #pragma unroll
        for (int n = 0; n < MN; n++) norm1 = fmaxf(norm1, col[n]);

        float u2 = u * u;
        float jn = u2 * sqrtf(norm1 * norminf);
        out[s0 + tid] = delta / (0.1f * jn);
    }
}

// ---------------------------------------------------------------------------
extern "C" void kernel_launch(void* const* d_in, const int* in_sizes, int n_in,
                              void* d_out, int out_size) {
    const float* data = (const float*)d_in[0];   // [2048,3,32,32]
    const float* W    = (const float*)d_in[1];   // [3072,10]
    const float* bias = (const float*)d_in[2];   // [10]
    float* out = (float*)d_out;                  // [2048,1]

    static int configured = 0;
    if (!configured) {
        cudaFuncSetAttribute(main_kernel,
                             cudaFuncAttributeMaxDynamicSharedMemorySize,
                             98304);
        configured = 1;
    }

    prep_kernel<<<22, 256>>>(W);
    main_kernel<<<256, 384, 98304>>>(data, bias, out);
}

// round 8
// speedup vs baseline: 1.0650x; 1.0650x over previous
#include <cuda_runtime.h>
#include <cstdint>
#include <math.h>

#define BN 2048
#define DN 3072
#define CN 10
#define MN 9

#define ALPHA  0.999999f             // 1 - C*NUM_STAB
#define NST    1e-7f
#define RS10   0.31622776601683794f  // 1/sqrt(10)

typedef unsigned long long u64;
typedef unsigned int u32;

// packed fp32x2 FMA: acc.{lo,hi} += a.{lo,hi} * b.{lo,hi}
#define FMA_X2(acc, a, b) \
    asm("fma.rn.f32x2 %0, %1, %2, %0;" : "+l"(acc) : "l"(a), "l"(b))
#define UNPACK_X2(lo, hi, v) \
    asm("mov.b64 {%0, %1}, %2;" : "=f"(lo), "=f"(hi) : "l"(v))

#define MBAR_INIT(a, n) \
    asm volatile("mbarrier.init.shared.b64 [%0], %1;" :: "r"(a), "r"(n) : "memory")
#define MBAR_EXPECT_TX(a, n) \
    asm volatile("mbarrier.arrive.expect_tx.shared.b64 _, [%0], %1;" :: "r"(a), "r"(n) : "memory")
// TMA bulk copy, CTA-scoped destination (sm_103a; shared::cta form per
// in-tree Blackwell examples)
#define CP_BULK_CTA(dst, src, bytes, mbar) \
    asm volatile("cp.async.bulk.shared::cta.global.mbarrier::complete_tx::bytes [%0], [%1], %2, [%3];" \
        :: "r"(dst), "l"(src), "r"(bytes), "r"(mbar) : "memory")

__device__ __forceinline__ void mbar_wait(u32 mbar, u32 parity) {
    u32 done;
    asm volatile(
        "{\n\t.reg .pred p;\n\t"
        "mbarrier.try_wait.parity.acquire.cta.shared::cta.b64 p, [%1], %2;\n\t"
        "selp.b32 %0, 1, 0, p;\n\t}"
        : "=r"(done) : "r"(mbar), "r"(parity) : "memory");
    if (!done) {
        asm volatile(
            "{\n\t.reg .pred P1;\n\t"
            "WL%=:\n\t"
            "mbarrier.try_wait.parity.acquire.cta.shared::cta.b64 P1, [%0], %1, 0x989680;\n\t"
            "@P1 bra.uni WD%=;\n\t"
            "bra.uni WL%=;\n\t"
            "WD%=:\n\t}"
            :: "r"(mbar), "r"(parity) : "memory");
    }
}

// Scratch (no allocations allowed)
__device__ __align__(16) float g_Wt[CN * DN];    // W transposed [C][D]
__device__ float g_Wg[CN * CN];                  // W^T W

// ---------------------------------------------------------------------------
// Prep: blocks 0..11 transpose W -> Wt; blocks 12..21 compute Wg rows.
// ---------------------------------------------------------------------------
__global__ void __launch_bounds__(256) prep_kernel(const float* __restrict__ W) {
    int bid = blockIdx.x;
    int tid = threadIdx.x;
    if (bid < 12) {
        int d = bid * 256 + tid;
        float w[CN];
        #pragma unroll
        for (int c = 0; c < CN; c++) w[c] = __ldg(&W[d * CN + c]);
        #pragma unroll
        for (int c = 0; c < CN; c++) g_Wt[c * DN + d] = w[c];
    } else {
        int i = bid - 12;
        float acc[CN];
        #pragma unroll
        for (int j = 0; j < CN; j++) acc[j] = 0.f;
        for (int d = tid; d < DN; d += 256) {
            float w[CN];
            #pragma unroll
            for (int j = 0; j < CN; j++) w[j] = __ldg(&W[d * CN + j]);
            float wi = w[i];
            #pragma unroll
            for (int j = 0; j < CN; j++) acc[j] = fmaf(wi, w[j], acc[j]);
        }
        #pragma unroll
        for (int j = 0; j < CN; j++) {
            #pragma unroll
            for (int off = 16; off > 0; off >>= 1)
                acc[j] += __shfl_xor_sync(0xffffffffu, acc[j], off);
        }
        __shared__ float smem[8][CN];
        int w_ = tid >> 5, l = tid & 31;
        if (l == 0) {
            #pragma unroll
            for (int j = 0; j < CN; j++) smem[w_][j] = acc[j];
        }
        __syncthreads();
        if (tid < CN) {
            float s = 0.f;
            #pragma unroll
            for (int k = 0; k < 8; k++) s += smem[k][tid];
            g_Wg[i * CN + tid] = s;
        }
    }
}

// ---------------------------------------------------------------------------
// Main kernel: 128 blocks x 512 threads, 16 samples/block, full K, one wave.
// x staged via TMA bulk (16 x 12KB, L2->SMEM direct, bypasses L1TEX fill).
// wid = octet(1b)|kidx(3b); lane = pgrp(2b)|klane(3b). FFMA2 from SMEM,
// W via __ldg. Fused epilogue.
// ---------------------------------------------------------------------------
extern __shared__ __align__(16) float4 xsm[];    // [16 samples][768 float4] = 192KB

__global__ void __launch_bounds__(512, 1) main_kernel(const float* __restrict__ data,
                                                      const float* __restrict__ bias,
                                                      float* __restrict__ out) {
    __shared__ __align__(8) u64 mbar_s;
    __shared__ float smred[8][16][CN];           // [kidx][sample][class]

    const int tid   = threadIdx.x;
    const int wid   = tid >> 5;
    const int lane  = tid & 31;
    const int kidx  = wid & 7;                   // K-eighth (96 float4)
    const int octet = wid >> 3;                  // sample half
    const int pgrp  = lane >> 3;                 // sample pair within half
    const int klane = lane & 7;

    const int ls = octet * 8 + pgrp * 2;         // local sample (pair base)
    const int s0 = blockIdx.x * 16;              // block's first sample

    const u32 mbar = (u32)__cvta_generic_to_shared(&mbar_s);
    const u32 xsa  = (u32)__cvta_generic_to_shared(xsm);

    if (tid == 0) MBAR_INIT(mbar, 1);
    __syncthreads();

    if (tid == 0) {
        MBAR_EXPECT_TX(mbar, 196608u);
        const char* src = reinterpret_cast<const char*>(data) + (size_t)s0 * (DN * 4);
        #pragma unroll
        for (int j = 0; j < 16; j++)
            CP_BULK_CTA(xsa + j * 12288u, src + (size_t)j * 12288u, 12288u, mbar);
    }
    mbar_wait(mbar, 0);

    // ---- compute: warp = 8 samples x K-eighth, FFMA2 pairs ---------------
    const ulonglong2* __restrict__ xs = reinterpret_cast<const ulonglong2*>(xsm);
    const ulonglong2* __restrict__ x0 = xs + (size_t)ls * 768 + kidx * 96 + klane;
    const ulonglong2* __restrict__ wt = reinterpret_cast<const ulonglong2*>(g_Wt);
    const int kw = kidx * 96 + klane;            // W float4 base index

    u64 a0[CN], a1[CN];
    #pragma unroll
    for (int c = 0; c < CN; c++) { a0[c] = 0ull; a1[c] = 0ull; }

    #pragma unroll
    for (int i = 0; i < 12; i++) {
        ulonglong2 xv0 = x0[i * 8];
        ulonglong2 xv1 = x0[768 + i * 8];
        #pragma unroll
        for (int c = 0; c < CN; c++) {
            ulonglong2 wv = __ldg(&wt[c * 768 + kw + i * 8]);
            FMA_X2(a0[c], xv0.x, wv.x);
            FMA_X2(a0[c], xv0.y, wv.y);
            FMA_X2(a1[c], xv1.x, wv.x);
            FMA_X2(a1[c], xv1.y, wv.y);
        }
    }

    float f0[CN], f1[CN];
    #pragma unroll
    for (int c = 0; c < CN; c++) {
        float lo, hi;
        UNPACK_X2(lo, hi, a0[c]); f0[c] = lo + hi;
        UNPACK_X2(lo, hi, a1[c]); f1[c] = lo + hi;
    }
    #pragma unroll
    for (int c = 0; c < CN; c++) {
        #pragma unroll
        for (int off = 4; off > 0; off >>= 1) {
            f0[c] += __shfl_xor_sync(0xffffffffu, f0[c], off);
            f1[c] += __shfl_xor_sync(0xffffffffu, f1[c], off);
        }
    }
    if (klane == 0) {
        #pragma unroll
        for (int c = 0; c < CN; c++) {
            smred[kidx][ls][c]     = f0[c];
            smred[kidx][ls + 1][c] = f1[c];
        }
    }
    __syncthreads();

    // ---- fused epilogue: 16 threads, one per sample ------------------------
    if (tid < 16) {
        float l[CN];
        #pragma unroll
        for (int c = 0; c < CN; c++) {
            float a = __ldg(&bias[c]);
            #pragma unroll
            for (int k = 0; k < 8; k++) a += smred[k][tid][c];
            l[c] = a;
        }

        float mx = l[0];
        #pragma unroll
        for (int c = 1; c < CN; c++) mx = fmaxf(mx, l[c]);

        float e[CN], Z = 0.f;
        #pragma unroll
        for (int c = 0; c < CN; c++) { e[c] = expf(l[c] - mx); Z += e[c]; }
        float invZ = 1.f / Z;

        float s[CN], r[CN], sumr = 0.f;
        #pragma unroll
        for (int c = 0; c < CN; c++) {
            s[c] = e[c] * invZ;
            float p = fmaf(s[c], ALPHA, NST);
            r[c] = sqrtf(p);
            sumr += r[c];
        }
        float u = 1.f - r[MN];
        float delta = 2.f * acosf(fminf(sumr * RS10, 1.f));

        float wg[CN * CN];
        #pragma unroll
        for (int v = 0; v < CN * CN; v++) wg[v] = __ldg(&g_Wg[v]);

        float q[CN];
        #pragma unroll
        for (int j = 0; j < CN; j++) {
            float a = 0.f;
            #pragma unroll
            for (int k = 0; k < CN; k++) a = fmaf(s[k], wg[k * CN + j], a);
            q[j] = a;
        }
        float qs = 0.f;
        #pragma unroll
        for (int j = 0; j < CN; j++) qs = fmaf(q[j], s[j], qs);

        float inv_u = 1.f / u;
        float c2com = ALPHA * s[MN] * inv_u * inv_u / r[MN];
        float c1[MN], c2[MN], t[MN];
        #pragma unroll
        for (int m = 0; m < MN; m++) {
            c1[m] = ALPHA * s[m] * inv_u / r[m];
            c2[m] = c2com * r[m];
            t[m]  = c1[m] + c2[m];
        }

        float col[MN];
        #pragma unroll
        for (int n = 0; n < MN; n++) col[n] = 0.f;
        float norminf = 0.f;

        #pragma unroll
        for (int m = 0; m < MN; m++) {
            float Mrow[CN];
            #pragma unroll
            for (int j = 0; j < CN; j++)
                Mrow[j] = c1[m] * wg[m * CN + j] + c2[m] * wg[MN * CN + j] - t[m] * q[j];
            float wm = c1[m] * q[m] + c2[m] * q[MN] - t[m] * qs;
            float rowsum = 0.f;
            #pragma unroll
            for (int n = 0; n < MN; n++) {
                float g2 = c1[n] * Mrow[n] + c2[n] * Mrow[MN] - t[n] * wm;
                float ag = fabsf(g2);
                rowsum += ag;
                col[n] += ag;
            }
            norminf = fmaxf(norminf, rowsum);
        }
        float norm1 = 0.f;
        #pragma unroll
        for (int n = 0; n < MN; n++) norm1 = fmaxf(norm1, col[n]);

        float u2 = u * u;
        float jn = u2 * sqrtf(norm1 * norminf);
        out[s0 + tid] = delta / (0.1f * jn);
    }
}

// ---------------------------------------------------------------------------
extern "C" void kernel_launch(void* const* d_in, const int* in_sizes, int n_in,
                              void* d_out, int out_size) {
    const float* data = (const float*)d_in[0];   // [2048,3,32,32]
    const float* W    = (const float*)d_in[1];   // [3072,10]
    const float* bias = (const float*)d_in[2];   // [10]
    float* out = (float*)d_out;                  // [2048,1]

    static int configured = 0;
    if (!configured) {
        cudaFuncSetAttribute(main_kernel,
                             cudaFuncAttributeMaxDynamicSharedMemorySize,
                             196608);
        configured = 1;
    }

    prep_kernel<<<22, 256>>>(W);
    main_kernel<<<128, 512, 196608>>>(data, bias, out);
}

// round 9
// speedup vs baseline: 1.1750x; 1.1033x over previous
#include <cuda_runtime.h>
#include <cstdint>
#include <math.h>

#define BN 2048
#define DN 3072
#define CN 10
#define MN 9

#define ALPHA  0.999999f             // 1 - C*NUM_STAB
#define NST    1e-7f
#define RS10   0.31622776601683794f  // 1/sqrt(10)

typedef unsigned long long u64;
typedef unsigned int u32;

// packed fp32x2 FMA: acc.{lo,hi} += a.{lo,hi} * b.{lo,hi}
#define FMA_X2(acc, a, b) \
    asm("fma.rn.f32x2 %0, %1, %2, %0;" : "+l"(acc) : "l"(a), "l"(b))
#define UNPACK_X2(lo, hi, v) \
    asm("mov.b64 {%0, %1}, %2;" : "=f"(lo), "=f"(hi) : "l"(v))

#define MBAR_INIT(a, n) \
    asm volatile("mbarrier.init.shared.b64 [%0], %1;" :: "r"(a), "r"(n) : "memory")
#define MBAR_EXPECT_TX(a, n) \
    asm volatile("mbarrier.arrive.expect_tx.shared.b64 _, [%0], %1;" :: "r"(a), "r"(n) : "memory")
#define CP_BULK_CTA(dst, src, bytes, mbar) \
    asm volatile("cp.async.bulk.shared::cta.global.mbarrier::complete_tx::bytes [%0], [%1], %2, [%3];" \
        :: "r"(dst), "l"(src), "r"(bytes), "r"(mbar) : "memory")

__device__ __forceinline__ void mbar_wait(u32 mbar, u32 parity) {
    u32 done;
    asm volatile(
        "{\n\t.reg .pred p;\n\t"
        "mbarrier.try_wait.parity.acquire.cta.shared::cta.b64 p, [%1], %2;\n\t"
        "selp.b32 %0, 1, 0, p;\n\t}"
        : "=r"(done) : "r"(mbar), "r"(parity) : "memory");
    if (!done) {
        asm volatile(
            "{\n\t.reg .pred P1;\n\t"
            "WL%=:\n\t"
            "mbarrier.try_wait.parity.acquire.cta.shared::cta.b64 P1, [%0], %1, 0x989680;\n\t"
            "@P1 bra.uni WD%=;\n\t"
            "bra.uni WL%=;\n\t"
            "WD%=:\n\t}"
            :: "r"(mbar), "r"(parity) : "memory");
    }
}

// Scratch (no allocations allowed)
__device__ __align__(16) float g_Wt[CN * DN];    // W transposed [C][D]
__device__ float g_Wg[CN * CN];                  // W^T W

// ---------------------------------------------------------------------------
// Prep: blocks 0..11 transpose W -> Wt; blocks 12..21 compute Wg rows.
// ---------------------------------------------------------------------------
__global__ void __launch_bounds__(256) prep_kernel(const float* __restrict__ W) {
    int bid = blockIdx.x;
    int tid = threadIdx.x;
    if (bid < 12) {
        int d = bid * 256 + tid;
        float w[CN];
        #pragma unroll
        for (int c = 0; c < CN; c++) w[c] = __ldg(&W[d * CN + c]);
        #pragma unroll
        for (int c = 0; c < CN; c++) g_Wt[c * DN + d] = w[c];
    } else {
        int i = bid - 12;
        float acc[CN];
        #pragma unroll
        for (int j = 0; j < CN; j++) acc[j] = 0.f;
        for (int d = tid; d < DN; d += 256) {
            float w[CN];
            #pragma unroll
            for (int j = 0; j < CN; j++) w[j] = __ldg(&W[d * CN + j]);
            float wi = w[i];
            #pragma unroll
            for (int j = 0; j < CN; j++) acc[j] = fmaf(wi, w[j], acc[j]);
        }
        #pragma unroll
        for (int j = 0; j < CN; j++) {
            #pragma unroll
            for (int off = 16; off > 0; off >>= 1)
                acc[j] += __shfl_xor_sync(0xffffffffu, acc[j], off);
        }
        __shared__ float smem[8][CN];
        int w_ = tid >> 5, l = tid & 31;
        if (l == 0) {
            #pragma unroll
            for (int j = 0; j < CN; j++) smem[w_][j] = acc[j];
        }
        __syncthreads();
        if (tid < CN) {
            float s = 0.f;
            #pragma unroll
            for (int k = 0; k < 8; k++) s += smem[k][tid];
            g_Wg[i * CN + tid] = s;
        }
    }
}

// ---------------------------------------------------------------------------
// Hybrid main kernel: 128 blocks x 512 threads, 16 samples/block.
// Samples 0-7: TMA bulk -> smem (96KB), consumed by warps 0-7.
// Samples 8-15: direct ld.global.cs, warps 8-15 (LSU engine in parallel
// with the TMA engine -> tests/exploits per-SM per-engine rate limit).
// Both halves: FFMA2, W via __ldg (L1-resident: smem ~101KB).
// Fused epilogue.
// ---------------------------------------------------------------------------
extern __shared__ __align__(16) float4 xsm[];    // [8 samples][768 float4] = 96KB

__global__ void __launch_bounds__(512, 1) main_kernel(const float* __restrict__ data,
                                                      const float* __restrict__ bias,
                                                      float* __restrict__ out) {
    __shared__ __align__(8) u64 mbar_s;
    __shared__ float smred[8][16][CN];           // [kidx][sample][class]

    const int tid   = threadIdx.x;
    const int wid   = tid >> 5;
    const int lane  = tid & 31;
    const int kidx  = wid & 7;                   // K-eighth (96 float4)
    const int octet = wid >> 3;                  // 0 = TMA half, 1 = LDG half
    const int pgrp  = lane >> 3;                 // sample pair within half
    const int klane = lane & 7;

    const int ls = pgrp * 2;                     // local sample within half
    const int s0 = blockIdx.x * 16;              // block's first sample

    const u32 mbar = (u32)__cvta_generic_to_shared(&mbar_s);
    const u32 xsa  = (u32)__cvta_generic_to_shared(xsm);

    if (tid == 0) MBAR_INIT(mbar, 1);
    __syncthreads();

    if (tid == 0) {
        MBAR_EXPECT_TX(mbar, 98304u);
        const char* src = reinterpret_cast<const char*>(data) + (size_t)s0 * (DN * 4);
        #pragma unroll
        for (int j = 0; j < 8; j++)
            CP_BULK_CTA(xsa + j * 12288u, src + (size_t)j * 12288u, 12288u, mbar);
    }

    const ulonglong2* __restrict__ wt = reinterpret_cast<const ulonglong2*>(g_Wt);
    const int kw = kidx * 96 + klane;            // W float4 base index

    u64 a0[CN], a1[CN];
    #pragma unroll
    for (int c = 0; c < CN; c++) { a0[c] = 0ull; a1[c] = 0ull; }

    if (octet == 0) {
        // ---- TMA half: wait for smem fill, compute from SMEM --------------
        mbar_wait(mbar, 0);
        const ulonglong2* __restrict__ xs = reinterpret_cast<const ulonglong2*>(xsm);
        const ulonglong2* __restrict__ x0 = xs + (size_t)ls * 768 + kw;
        #pragma unroll
        for (int i = 0; i < 12; i++) {
            ulonglong2 xv0 = x0[i * 8];
            ulonglong2 xv1 = x0[768 + i * 8];
            #pragma unroll
            for (int c = 0; c < CN; c++) {
                ulonglong2 wv = __ldg(&wt[c * 768 + kw + i * 8]);
                FMA_X2(a0[c], xv0.x, wv.x);
                FMA_X2(a0[c], xv0.y, wv.y);
                FMA_X2(a1[c], xv1.x, wv.x);
                FMA_X2(a1[c], xv1.y, wv.y);
            }
        }
    } else {
        // ---- LDG half: stream directly from gmem (LSU engine) -------------
        const char* xb0 = reinterpret_cast<const char*>(data)
                        + (size_t)(s0 + 8 + ls) * (DN * 4);
        const char* xb1 = xb0 + DN * 4;
        #pragma unroll 4
        for (int i = 0; i < 12; i++) {
            int k4 = kw + i * 8;
            u64 x0lo, x0hi, x1lo, x1hi;
            asm("ld.global.cs.v2.u64 {%0, %1}, [%2];"
                : "=l"(x0lo), "=l"(x0hi) : "l"(xb0 + (size_t)k4 * 16));
            asm("ld.global.cs.v2.u64 {%0, %1}, [%2];"
                : "=l"(x1lo), "=l"(x1hi) : "l"(xb1 + (size_t)k4 * 16));
            #pragma unroll
            for (int c = 0; c < CN; c++) {
                ulonglong2 wv = __ldg(&wt[c * 768 + kw + i * 8]);
                FMA_X2(a0[c], x0lo, wv.x);
                FMA_X2(a0[c], x0hi, wv.y);
                FMA_X2(a1[c], x1lo, wv.x);
                FMA_X2(a1[c], x1hi, wv.y);
            }
        }
    }

    // unpack, reduce across 8 klanes (xor 1,2,4 stay within pgrp)
    float f0[CN], f1[CN];
    #pragma unroll
    for (int c = 0; c < CN; c++) {
        float lo, hi;
        UNPACK_X2(lo, hi, a0[c]); f0[c] = lo + hi;
        UNPACK_X2(lo, hi, a1[c]); f1[c] = lo + hi;
    }
    #pragma unroll
    for (int c = 0; c < CN; c++) {
        #pragma unroll
        for (int off = 4; off > 0; off >>= 1) {
            f0[c] += __shfl_xor_sync(0xffffffffu, f0[c], off);
            f1[c] += __shfl_xor_sync(0xffffffffu, f1[c], off);
        }
    }
    if (klane == 0) {
        int srow = octet * 8 + ls;
        #pragma unroll
        for (int c = 0; c < CN; c++) {
            smred[kidx][srow][c]     = f0[c];
            smred[kidx][srow + 1][c] = f1[c];
        }
    }
    __syncthreads();

    // ---- fused epilogue: 16 threads, one per sample ------------------------
    if (tid < 16) {
        float l[CN];
        #pragma unroll
        for (int c = 0; c < CN; c++) {
            float a = __ldg(&bias[c]);
            #pragma unroll
            for (int k = 0; k < 8; k++) a += smred[k][tid][c];
            l[c] = a;
        }

        float mx = l[0];
        #pragma unroll
        for (int c = 1; c < CN; c++) mx = fmaxf(mx, l[c]);

        float e[CN], Z = 0.f;
        #pragma unroll
        for (int c = 0; c < CN; c++) { e[c] = expf(l[c] - mx); Z += e[c]; }
        float invZ = 1.f / Z;

        float s[CN], r[CN], sumr = 0.f;
        #pragma unroll
        for (int c = 0; c < CN; c++) {
            s[c] = e[c] * invZ;
            float p = fmaf(s[c], ALPHA, NST);
            r[c] = sqrtf(p);
            sumr += r[c];
        }
        float u = 1.f - r[MN];
        float delta = 2.f * acosf(fminf(sumr * RS10, 1.f));

        float wg[CN * CN];
        #pragma unroll
        for (int v = 0; v < CN * CN; v++) wg[v] = __ldg(&g_Wg[v]);

        float q[CN];
        #pragma unroll
        for (int j = 0; j < CN; j++) {
            float a = 0.f;
            #pragma unroll
            for (int k = 0; k < CN; k++) a = fmaf(s[k], wg[k * CN + j], a);
            q[j] = a;
        }
        float qs = 0.f;
        #pragma unroll
        for (int j = 0; j < CN; j++) qs = fmaf(q[j], s[j], qs);

        float inv_u = 1.f / u;
        float c2com = ALPHA * s[MN] * inv_u * inv_u / r[MN];
        float c1[MN], c2[MN], t[MN];
        #pragma unroll
        for (int m = 0; m < MN; m++) {
            c1[m] = ALPHA * s[m] * inv_u / r[m];
            c2[m] = c2com * r[m];
            t[m]  = c1[m] + c2[m];
        }

        float col[MN];
        #pragma unroll
        for (int n = 0; n < MN; n++) col[n] = 0.f;
        float norminf = 0.f;

        #pragma unroll
        for (int m = 0; m < MN; m++) {
            float Mrow[CN];
            #pragma unroll
            for (int j = 0; j < CN; j++)
                Mrow[j] = c1[m] * wg[m * CN + j] + c2[m] * wg[MN * CN + j] - t[m] * q[j];
            float wm = c1[m] * q[m] + c2[m] * q[MN] - t[m] * qs;
            float rowsum = 0.f;
            #pragma unroll
            for (int n = 0; n < MN; n++) {
                float g2 = c1[n] * Mrow[n] + c2[n] * Mrow[MN] - t[n] * wm;
                float ag = fabsf(g2);
                rowsum += ag;
                col[n] += ag;
            }
            norminf = fmaxf(norminf, rowsum);
        }
        float norm1 = 0.f;
        #pragma unroll
        for (int n = 0; n < MN; n++) norm1 = fmaxf(norm1, col[n]);

        float u2 = u * u;
        float jn = u2 * sqrtf(norm1 * norminf);
        out[s0 + tid] = delta / (0.1f * jn);
    }
}

// ---------------------------------------------------------------------------
extern "C" void kernel_launch(void* const* d_in, const int* in_sizes, int n_in,
                              void* d_out, int out_size) {
    const float* data = (const float*)d_in[0];   // [2048,3,32,32]
    const float* W    = (const float*)d_in[1];   // [3072,10]
    const float* bias = (const float*)d_in[2];   // [10]
    float* out = (float*)d_out;                  // [2048,1]

    static int configured = 0;
    if (!configured) {
        cudaFuncSetAttribute(main_kernel,
                             cudaFuncAttributeMaxDynamicSharedMemorySize,
                             98304 + 10240);
        configured = 1;
    }

    prep_kernel<<<22, 256>>>(W);
    main_kernel<<<128, 512, 98304>>>(data, bias, out);
}

// round 10
// speedup vs baseline: 1.1909x; 1.0135x over previous
#include <cuda_runtime.h>
#include <cstdint>
#include <math.h>

#define BN 2048
#define DN 3072
#define CN 10
#define MN 9

#define ALPHA  0.999999f             // 1 - C*NUM_STAB
#define NST    1e-7f
#define RS10   0.31622776601683794f  // 1/sqrt(10)

typedef unsigned long long u64;
typedef unsigned int u32;

// packed fp32x2 FMA: acc.{lo,hi} += a.{lo,hi} * b.{lo,hi}
#define FMA_X2(acc, a, b) \
    asm("fma.rn.f32x2 %0, %1, %2, %0;" : "+l"(acc) : "l"(a), "l"(b))
#define UNPACK_X2(lo, hi, v) \
    asm("mov.b64 {%0, %1}, %2;" : "=f"(lo), "=f"(hi) : "l"(v))

#define MBAR_INIT(a, n) \
    asm volatile("mbarrier.init.shared.b64 [%0], %1;" :: "r"(a), "r"(n) : "memory")
#define MBAR_EXPECT_TX(a, n) \
    asm volatile("mbarrier.arrive.expect_tx.shared.b64 _, [%0], %1;" :: "r"(a), "r"(n) : "memory")
#define CP_BULK_CTA(dst, src, bytes, mbar) \
    asm volatile("cp.async.bulk.shared::cta.global.mbarrier::complete_tx::bytes [%0], [%1], %2, [%3];" \
        :: "r"(dst), "l"(src), "r"(bytes), "r"(mbar) : "memory")

__device__ __forceinline__ void mbar_wait(u32 mbar, u32 parity) {
    u32 done;
    asm volatile(
        "{\n\t.reg .pred p;\n\t"
        "mbarrier.try_wait.parity.acquire.cta.shared::cta.b64 p, [%1], %2;\n\t"
        "selp.b32 %0, 1, 0, p;\n\t}"
        : "=r"(done) : "r"(mbar), "r"(parity) : "memory");
    if (!done) {
        asm volatile(
            "{\n\t.reg .pred P1;\n\t"
            "WL%=:\n\t"
            "mbarrier.try_wait.parity.acquire.cta.shared::cta.b64 P1, [%0], %1, 0x989680;\n\t"
            "@P1 bra.uni WD%=;\n\t"
            "bra.uni WL%=;\n\t"
            "WD%=:\n\t}"
            :: "r"(mbar), "r"(parity) : "memory");
    }
}

// Scratch (no allocations allowed)
__device__ __align__(16) float g_Wt[CN * DN];    // W transposed [C][D]
__device__ float g_Wg[CN * CN];                  // W^T W

// ---------------------------------------------------------------------------
// Prep: blocks 0..11 transpose W -> Wt; blocks 12..21 compute Wg rows.
// ---------------------------------------------------------------------------
__global__ void __launch_bounds__(256) prep_kernel(const float* __restrict__ W) {
    int bid = blockIdx.x;
    int tid = threadIdx.x;
    if (bid < 12) {
        int d = bid * 256 + tid;
        float w[CN];
        #pragma unroll
        for (int c = 0; c < CN; c++) w[c] = __ldg(&W[d * CN + c]);
        #pragma unroll
        for (int c = 0; c < CN; c++) g_Wt[c * DN + d] = w[c];
    } else {
        int i = bid - 12;
        float acc[CN];
        #pragma unroll
        for (int j = 0; j < CN; j++) acc[j] = 0.f;
        for (int d = tid; d < DN; d += 256) {
            float w[CN];
            #pragma unroll
            for (int j = 0; j < CN; j++) w[j] = __ldg(&W[d * CN + j]);
            float wi = w[i];
            #pragma unroll
            for (int j = 0; j < CN; j++) acc[j] = fmaf(wi, w[j], acc[j]);
        }
        #pragma unroll
        for (int j = 0; j < CN; j++) {
            #pragma unroll
            for (int off = 16; off > 0; off >>= 1)
                acc[j] += __shfl_xor_sync(0xffffffffu, acc[j], off);
        }
        __shared__ float smem[8][CN];
        int w_ = tid >> 5, l = tid & 31;
        if (l == 0) {
            #pragma unroll
            for (int j = 0; j < CN; j++) smem[w_][j] = acc[j];
        }
        __syncthreads();
        if (tid < CN) {
            float s = 0.f;
            #pragma unroll
            for (int k = 0; k < 8; k++) s += smem[k][tid];
            g_Wg[i * CN + tid] = s;
        }
    }
}

// ---------------------------------------------------------------------------
// Hybrid main kernel (pipelined TMA): 128 blocks x 512 threads, 16 samples.
// Samples 0-7: TMA bulk -> smem in 4 K-QUARTERS (4 mbarriers; warp kidx
// waits only on quarter kidx>>1 -> compute starts after first 24KB).
// Samples 8-15: direct ld.global.cs (LSU engine runs concurrently with TMA).
// Both halves: FFMA2, W via __ldg. Fused epilogue.
// ---------------------------------------------------------------------------
extern __shared__ __align__(16) float4 xsm[];    // [8 samples][768 float4] = 96KB

__global__ void __launch_bounds__(512, 1) main_kernel(const float* __restrict__ data,
                                                      const float* __restrict__ bias,
                                                      float* __restrict__ out) {
    __shared__ __align__(8) u64 mbar_s[4];       // one per K-quarter
    __shared__ float smred[8][16][CN];           // [kidx][sample][class]

    const int tid   = threadIdx.x;
    const int wid   = tid >> 5;
    const int lane  = tid & 31;
    const int kidx  = wid & 7;                   // K-eighth (96 float4)
    const int octet = wid >> 3;                  // 0 = TMA half, 1 = LDG half
    const int pgrp  = lane >> 3;                 // sample pair within half
    const int klane = lane & 7;

    const int ls = pgrp * 2;                     // local sample within half
    const int s0 = blockIdx.x * 16;              // block's first sample

    const u32 mb0  = (u32)__cvta_generic_to_shared(&mbar_s[0]);
    const u32 xsa  = (u32)__cvta_generic_to_shared(xsm);

    if (tid == 0) {
        #pragma unroll
        for (int q = 0; q < 4; q++) MBAR_INIT(mb0 + q * 8, 1);
    }
    __syncthreads();

    if (tid == 0) {
        const char* src = reinterpret_cast<const char*>(data) + (size_t)s0 * (DN * 4);
        #pragma unroll
        for (int q = 0; q < 4; q++) {
            MBAR_EXPECT_TX(mb0 + q * 8, 24576u);        // 8 samples x 3KB
            #pragma unroll
            for (int j = 0; j < 8; j++)
                CP_BULK_CTA(xsa + j * 12288u + q * 3072u,
                            src + (size_t)j * 12288u + q * 3072u,
                            3072u, mb0 + q * 8);
        }
    }

    const ulonglong2* __restrict__ wt = reinterpret_cast<const ulonglong2*>(g_Wt);
    const int kw = kidx * 96 + klane;            // W float4 base index

    u64 a0[CN], a1[CN];
    #pragma unroll
    for (int c = 0; c < CN; c++) { a0[c] = 0ull; a1[c] = 0ull; }

    if (octet == 0) {
        // ---- TMA half: wait only on our K-quarter, compute from SMEM ------
        mbar_wait(mb0 + (kidx >> 1) * 8, 0);
        const ulonglong2* __restrict__ xs = reinterpret_cast<const ulonglong2*>(xsm);
        const ulonglong2* __restrict__ x0 = xs + (size_t)ls * 768 + kw;
        #pragma unroll
        for (int i = 0; i < 12; i++) {
            ulonglong2 xv0 = x0[i * 8];
            ulonglong2 xv1 = x0[768 + i * 8];
            #pragma unroll
            for (int c = 0; c < CN; c++) {
                ulonglong2 wv = __ldg(&wt[c * 768 + kw + i * 8]);
                FMA_X2(a0[c], xv0.x, wv.x);
                FMA_X2(a0[c], xv0.y, wv.y);
                FMA_X2(a1[c], xv1.x, wv.x);
                FMA_X2(a1[c], xv1.y, wv.y);
            }
        }
    } else {
        // ---- LDG half: stream directly from gmem (LSU engine) -------------
        const char* xb0 = reinterpret_cast<const char*>(data)
                        + (size_t)(s0 + 8 + ls) * (DN * 4);
        const char* xb1 = xb0 + DN * 4;
        #pragma unroll 4
        for (int i = 0; i < 12; i++) {
            int k4 = kw + i * 8;
            u64 x0lo, x0hi, x1lo, x1hi;
            asm("ld.global.cs.v2.u64 {%0, %1}, [%2];"
                : "=l"(x0lo), "=l"(x0hi) : "l"(xb0 + (size_t)k4 * 16));
            asm("ld.global.cs.v2.u64 {%0, %1}, [%2];"
                : "=l"(x1lo), "=l"(x1hi) : "l"(xb1 + (size_t)k4 * 16));
            #pragma unroll
            for (int c = 0; c < CN; c++) {
                ulonglong2 wv = __ldg(&wt[c * 768 + kw + i * 8]);
                FMA_X2(a0[c], x0lo, wv.x);
                FMA_X2(a0[c], x0hi, wv.y);
                FMA_X2(a1[c], x1lo, wv.x);
                FMA_X2(a1[c], x1hi, wv.y);
            }
        }
    }

    // unpack, reduce across 8 klanes (xor 1,2,4 stay within pgrp)
    float f0[CN], f1[CN];
    #pragma unroll
    for (int c = 0; c < CN; c++) {
        float lo, hi;
        UNPACK_X2(lo, hi, a0[c]); f0[c] = lo + hi;
        UNPACK_X2(lo, hi, a1[c]); f1[c] = lo + hi;
    }
    #pragma unroll
    for (int c = 0; c < CN; c++) {
        #pragma unroll
        for (int off = 4; off > 0; off >>= 1) {
            f0[c] += __shfl_xor_sync(0xffffffffu, f0[c], off);
            f1[c] += __shfl_xor_sync(0xffffffffu, f1[c], off);
        }
    }
    if (klane == 0) {
        int srow = octet * 8 + ls;
        #pragma unroll
        for (int c = 0; c < CN; c++) {
            smred[kidx][srow][c]     = f0[c];
            smred[kidx][srow + 1][c] = f1[c];
        }
    }
    __syncthreads();

    // ---- fused epilogue: 16 threads, one per sample ------------------------
    if (tid < 16) {
        float l[CN];
        #pragma unroll
        for (int c = 0; c < CN; c++) {
            float a = __ldg(&bias[c]);
            #pragma unroll
            for (int k = 0; k < 8; k++) a += smred[k][tid][c];
            l[c] = a;
        }

        float mx = l[0];
        #pragma unroll
        for (int c = 1; c < CN; c++) mx = fmaxf(mx, l[c]);

        float e[CN], Z = 0.f;
        #pragma unroll
        for (int c = 0; c < CN; c++) { e[c] = expf(l[c] - mx); Z += e[c]; }
        float invZ = 1.f / Z;

        float s[CN], r[CN], sumr = 0.f;
        #pragma unroll
        for (int c = 0; c < CN; c++) {
            s[c] = e[c] * invZ;
            float p = fmaf(s[c], ALPHA, NST);
            r[c] = sqrtf(p);
            sumr += r[c];
        }
        float u = 1.f - r[MN];
        float delta = 2.f * acosf(fminf(sumr * RS10, 1.f));

        float wg[CN * CN];
        #pragma unroll
        for (int v = 0; v < CN * CN; v++) wg[v] = __ldg(&g_Wg[v]);

        float q[CN];
        #pragma unroll
        for (int j = 0; j < CN; j++) {
            float a = 0.f;
            #pragma unroll
            for (int k = 0; k < CN; k++) a = fmaf(s[k], wg[k * CN + j], a);
            q[j] = a;
        }
        float qs = 0.f;
        #pragma unroll
        for (int j = 0; j < CN; j++) qs = fmaf(q[j], s[j], qs);

        float inv_u = 1.f / u;
        float c2com = ALPHA * s[MN] * inv_u * inv_u / r[MN];
        float c1[MN], c2[MN], t[MN];
        #pragma unroll
        for (int m = 0; m < MN; m++) {
            c1[m] = ALPHA * s[m] * inv_u / r[m];
            c2[m] = c2com * r[m];
            t[m]  = c1[m] + c2[m];
        }

        float col[MN];
        #pragma unroll
        for (int n = 0; n < MN; n++) col[n] = 0.f;
        float norminf = 0.f;

        #pragma unroll
        for (int m = 0; m < MN; m++) {
            float Mrow[CN];
            #pragma unroll
            for (int j = 0; j < CN; j++)
                Mrow[j] = c1[m] * wg[m * CN + j] + c2[m] * wg[MN * CN + j] - t[m] * q[j];
            float wm = c1[m] * q[m] + c2[m] * q[MN] - t[m] * qs;
            float rowsum = 0.f;
            #pragma unroll
            for (int n = 0; n < MN; n++) {
                float g2 = c1[n] * Mrow[n] + c2[n] * Mrow[MN] - t[n] * wm;
                float ag = fabsf(g2);
                rowsum += ag;
                col[n] += ag;
            }
            norminf = fmaxf(norminf, rowsum);
        }
        float norm1 = 0.f;
        #pragma unroll
        for (int n = 0; n < MN; n++) norm1 = fmaxf(norm1, col[n]);

        float u2 = u * u;
        float jn = u2 * sqrtf(norm1 * norminf);
        out[s0 + tid] = delta / (0.1f * jn);
    }
}

// ---------------------------------------------------------------------------
extern "C" void kernel_launch(void* const* d_in, const int* in_sizes, int n_in,
                              void* d_out, int out_size) {
    const float* data = (const float*)d_in[0];   // [2048,3,32,32]
    const float* W    = (const float*)d_in[1];   // [3072,10]
    const float* bias = (const float*)d_in[2];   // [10]
    float* out = (float*)d_out;                  // [2048,1]

    static int configured = 0;
    if (!configured) {
        cudaFuncSetAttribute(main_kernel,
                             cudaFuncAttributeMaxDynamicSharedMemorySize,
                             98304 + 10240);
        configured = 1;
    }

    prep_kernel<<<22, 256>>>(W);
    main_kernel<<<128, 512, 98304>>>(data, bias, out);
}